// round 16
// baseline (speedup 1.0000x reference)
#include <cuda_runtime.h>
#include <cstdint>

// ---------------------------------------------------------------------------
// Problem constants
// ---------------------------------------------------------------------------
constexpr int BATCH = 4;
constexpr int N0    = 4096;   // input points
constexpr int N1    = 2048;   // after fps1
constexpr int N2    = 1024;   // after fps2 (DOWN_NUM)

// output layout (floats), tuple flattened in order:
// coor (B,3,1024), f (B,128,1024), xyz1 (B,3,2048), point1 (B,64,2048), inpc_f (B,8,4096)
constexpr size_t OUT_COOR   = 0;
constexpr size_t OUT_F      = OUT_COOR   + (size_t)BATCH * 3 * N2;
constexpr size_t OUT_XYZ1   = OUT_F      + (size_t)BATCH * 128 * N2;
constexpr size_t OUT_POINT1 = OUT_XYZ1   + (size_t)BATCH * 3 * N1;
constexpr size_t OUT_INPC   = OUT_POINT1 + (size_t)BATCH * 64 * N1;

// fps1 smem padding: exclusive SMs (launched onto an idle machine, FIFO).
// fps2 uses EXACT smem so it co-schedules with knn3 and starts immediately.
constexpr size_t FPS_SMEM_PAD = 200 * 1024;

// ---------------------------------------------------------------------------
// Device scratch (static; allocation is forbidden)
// ---------------------------------------------------------------------------
__device__ float  g_f0 [BATCH * N0 * 8];        // (B,N,C)
__device__ float4 g_pts0[BATCH * N0];
__device__ int    g_knn1[BATCH * N0 * 16];
__device__ int    g_knn2[BATCH * N1 * 16];      // gathered from knn1
__device__ int    g_knn3[BATCH * N1 * 16];
__device__ int    g_knn4[BATCH * N2 * 16];      // gathered from knn3
__device__ float  g_h   [BATCH * 32 * N0 * 16]; // reused by all convs (main-stream serial)
__device__ float  g_fa  [BATCH * N0 * 32];      // f1 (B,N,C)
__device__ int    g_fps1[BATCH * N1];
__device__ float4 g_pts1[BATCH * N1];
__device__ float  g_fqa [BATCH * N1 * 32];
__device__ float  g_fb  [BATCH * N1 * 64];      // f2
__device__ float  g_fc  [BATCH * N1 * 64];      // f3
__device__ int    g_fps2[BATCH * N2];
__device__ float4 g_pts2[BATCH * N2];
__device__ float  g_fqb [BATCH * N2 * 64];
__device__ float  g_psum[16 * 1024];
__device__ float  g_psq [16 * 1024];
__device__ float2 g_stats[16];

// monotone float->uint transform (ascending uint order == ascending float order)
__device__ __forceinline__ unsigned int ftrans(float f)
{
    unsigned int b = __float_as_uint(f);
    return (b & 0x80000000u) ? ~b : (b | 0x80000000u);
}

// packed f32x2 helpers (Blackwell): per-lane IEEE rn, bitwise == scalar ops
__device__ __forceinline__ unsigned long long pack2(float lo, float hi)
{
    unsigned long long r;
    asm("mov.b64 %0, {%1, %2};" : "=l"(r)
        : "r"(__float_as_uint(lo)), "r"(__float_as_uint(hi)));
    return r;
}
__device__ __forceinline__ void unpack2(float& lo, float& hi, unsigned long long v)
{
    unsigned int a, b;
    asm("mov.b64 {%0, %1}, %2;" : "=r"(a), "=r"(b) : "l"(v));
    lo = __uint_as_float(a); hi = __uint_as_float(b);
}
__device__ __forceinline__ unsigned long long addx2(unsigned long long a, unsigned long long b)
{
    unsigned long long r;
    asm("add.rn.f32x2 %0, %1, %2;" : "=l"(r) : "l"(a), "l"(b));
    return r;
}
__device__ __forceinline__ unsigned long long mulx2(unsigned long long a, unsigned long long b)
{
    unsigned long long r;
    asm("mul.rn.f32x2 %0, %1, %2;" : "=l"(r) : "l"(a), "l"(b));
    return r;
}

// ---------------------------------------------------------------------------
// prep: f0 = w_in @ x + b_in ; pts0 = (x,y,z,|p|^2) ; write inpc_f output
// ---------------------------------------------------------------------------
__global__ void k_prep0(const float* __restrict__ x, const float* __restrict__ w_in,
                        const float* __restrict__ b_in, float* __restrict__ f0,
                        float4* __restrict__ pts, float* __restrict__ out_inpc)
{
    int i = blockIdx.x * 256 + threadIdx.x;
    if (i >= BATCH * N0) return;
    int b = i / N0, n = i % N0;
    const float* xb = x + (size_t)b * 3 * N0 + n;
    float px = xb[0], py = xb[N0], pz = xb[2 * N0];
    float nrm = __fadd_rn(__fadd_rn(__fmul_rn(px, px), __fmul_rn(py, py)), __fmul_rn(pz, pz));
    pts[i] = make_float4(px, py, pz, nrm);
#pragma unroll
    for (int o = 0; o < 8; ++o) {
        float v = fmaf(w_in[o * 3 + 2], pz, fmaf(w_in[o * 3 + 1], py, w_in[o * 3] * px)) + b_in[o];
        f0[(size_t)i * 8 + o] = v;
        out_inpc[((size_t)b * 8 + o) * N0 + n] = v;
    }
}

// ---------------------------------------------------------------------------
// KNN, segmented x4 (measured-best): 4 threads per query, each scans a
// disjoint quarter of the key range with a private register top-16; stable
// 4-way merge in shared. Block = 128 threads = 32 queries x 4 segments.
// ---------------------------------------------------------------------------
__global__ void k_knn(const float4* __restrict__ ptsq, const float4* __restrict__ ptsk,
                      int Nq, int Nk, int* __restrict__ idx)
{
    constexpr int TILE = 256;
    __shared__ float4 sk[4 * TILE];                 // 16 KB staged keys
    __shared__ unsigned long long sl[32 * 65];      // padded candidate lists

    const int b   = blockIdx.y;
    const int tid = threadIdx.x;
    const int ql  = tid >> 2;          // query within block (0..31)
    const int s   = tid & 3;           // segment
    const int q   = blockIdx.x * 32 + ql;
    const int seglen  = Nk >> 2;
    const int segbase = s * seglen;

    float4 Q = ptsq[(size_t)b * Nq + q];

    float dist[16];
    int   ind [16];
#pragma unroll
    for (int i = 0; i < 16; ++i) { dist[i] = 3.4e38f; ind[i] = 0; }

    for (int t0 = 0; t0 < seglen; t0 += TILE) {
        __syncthreads();
        for (int j = tid; j < 4 * TILE; j += 128)
            sk[j] = ptsk[(size_t)b * Nk + (j >> 8) * seglen + t0 + (j & 255)];
        __syncthreads();
        const float4* mysk = sk + s * TILE;
#pragma unroll 4
        for (int j = 0; j < TILE; ++j) {
            float4 P = mysk[j];
            float dot = fmaf(Q.x, P.x, fmaf(Q.y, P.y, Q.z * P.z));
            float d = fmaf(-2.0f, dot, Q.w + P.w);
            if (d < dist[15]) {
                dist[15] = d; ind[15] = segbase + t0 + j;
#pragma unroll
                for (int t = 15; t > 0; --t) {
                    if (dist[t] < dist[t - 1]) {
                        float td = dist[t]; dist[t] = dist[t - 1]; dist[t - 1] = td;
                        int   ti = ind[t];  ind[t]  = ind[t - 1];  ind[t - 1]  = ti;
                    }
                }
            }
        }
    }

    unsigned long long* L = sl + (size_t)ql * 65 + (size_t)s * 16;
#pragma unroll
    for (int i = 0; i < 16; ++i)
        L[i] = ((unsigned long long)ftrans(dist[i]) << 32) | (unsigned int)ind[i];
    __syncthreads();

    if (s == 0) {
        const unsigned long long* M = sl + (size_t)ql * 65;
        int h0 = 0, h1 = 0, h2 = 0, h3 = 0;
        int* op = idx + ((size_t)b * Nq + q) * 16;
#pragma unroll
        for (int r = 0; r < 16; ++r) {
            unsigned long long b0 = (h0 < 16) ? M[h0]      : ~0ULL;
            unsigned long long b1 = (h1 < 16) ? M[16 + h1] : ~0ULL;
            unsigned long long b2 = (h2 < 16) ? M[32 + h2] : ~0ULL;
            unsigned long long b3 = (h3 < 16) ? M[48 + h3] : ~0ULL;
            unsigned long long m01 = b0 < b1 ? b0 : b1;
            unsigned long long m23 = b2 < b3 ? b2 : b3;
            unsigned long long m   = m01 < m23 ? m01 : m23;
            op[r] = (int)(unsigned int)m;
            if      (m == b0) ++h0;
            else if (m == b1) ++h1;
            else if (m == b2) ++h2;
            else              ++h3;
        }
    }
}

// knnOut[b][j][:] = knnIn[b][fidx[b][j]][:]  — exact row gather.
// Valid because queries pts_sub = pts_full[fidx] bit-exactly and the key set
// is identical, so the deterministic top-16 rows coincide.
__global__ void k_knn_gather(const int* __restrict__ fidx, const int* __restrict__ knnIn,
                             int NinQ, int Nout, int* __restrict__ knnOut)
{
    int i = blockIdx.x * 256 + threadIdx.x;
    int total = BATCH * Nout * 16;
    if (i >= total) return;
    int r = i & 15;
    int j = (i >> 4) % Nout;
    int b = i / (Nout * 16);
    int src = fidx[(size_t)b * Nout + j];
    knnOut[i] = knnIn[((size_t)b * NinQ + src) * 16 + r];
}

// ---------------------------------------------------------------------------
// FPS + fused gather epilogue, BARRIER-FREE iterations.
// Per-warp partials carry a 16-bit iteration tag:
//   partial = (distbits<<32) | ((it&0xffff)<<16) | (0xffff - idx)
// All tags equal within an iteration -> u64 order == (dist, ~idx) order ->
// exact first-index tie-break. Warps publish via volatile STS.64 and spin on
// the NW tagged slots (double-buffered by it&1; a warp can only overwrite a
// buffer after proving every warp consumed its previous generation).
// ---------------------------------------------------------------------------
template <int NPTS, int M, int TPB>
__global__ void k_fps(const float4* __restrict__ pts, int* __restrict__ out,
                      float4* __restrict__ ptsOut, float* __restrict__ out_xyz)
{
    constexpr int PPT = NPTS / TPB;
    constexpr int PP  = PPT / 2;
    constexpr int NW  = TPB / 32;
    extern __shared__ float4 spts[];                          // NPTS float4
    int* sidx = (int*)(spts + NPTS);                          // M ints
    unsigned long long* sred = (unsigned long long*)(sidx + M);  // [2][NW]

    const int b = blockIdx.x, t = threadIdx.x;
    const int wid = t >> 5, lane = t & 31;

    // init sentinel tags (seq=0xffff never matches it < 65535)
    if (t < 2 * NW) sred[t] = 0xffff0000ull;

    unsigned long long lx2[PP], ly2[PP], lz2[PP];
    float ld[PPT];
#pragma unroll
    for (int i = 0; i < PP; ++i) {
        float4 p0 = pts[(size_t)b * NPTS + (2 * i) * TPB + t];
        float4 p1 = pts[(size_t)b * NPTS + (2 * i + 1) * TPB + t];
        lx2[i] = pack2(p0.x, p1.x);
        ly2[i] = pack2(p0.y, p1.y);
        lz2[i] = pack2(p0.z, p1.z);
        ld[2 * i] = 1e10f; ld[2 * i + 1] = 1e10f;
        spts[(2 * i) * TPB + t] = p0;
        spts[(2 * i + 1) * TPB + t] = p1;
    }
    __syncthreads();

    volatile unsigned long long* vred = (volatile unsigned long long*)sred;

    int far = 0;
    for (int it = 0; it < M; ++it) {
        if (t == 0) sidx[it] = far;
        float4 c = spts[far];
        unsigned long long ncx2 = pack2(-c.x, -c.x);
        unsigned long long ncy2 = pack2(-c.y, -c.y);
        unsigned long long ncz2 = pack2(-c.z, -c.z);

        float bv = -1.0f; int bi = 0;
#pragma unroll
        for (int i = 0; i < PP; ++i) {
            unsigned long long dx2 = addx2(lx2[i], ncx2);   // == __fsub_rn
            unsigned long long dy2 = addx2(ly2[i], ncy2);
            unsigned long long dz2 = addx2(lz2[i], ncz2);
            unsigned long long xx2 = mulx2(dx2, dx2);
            unsigned long long yy2 = mulx2(dy2, dy2);
            unsigned long long zz2 = mulx2(dz2, dz2);
            unsigned long long s2  = addx2(xx2, yy2);
            unsigned long long d2  = addx2(s2, zz2);
            float d0, d1; unpack2(d0, d1, d2);
            float nd0 = fminf(ld[2 * i], d0);     ld[2 * i] = nd0;
            float nd1 = fminf(ld[2 * i + 1], d1); ld[2 * i + 1] = nd1;
            if (nd0 > bv) { bv = nd0; bi = (2 * i) * TPB + t; }
            if (nd1 > bv) { bv = nd1; bi = (2 * i + 1) * TPB + t; }
        }
        // warp argmax: dist >= 0 so float bits compare as uints
        unsigned int vb   = __float_as_uint(bv);
        unsigned int wmax = __reduce_max_sync(0xffffffffu, vb);
        unsigned int cand = (vb == wmax) ? (unsigned int)bi : 0xffffffffu;
        unsigned int wmin = __reduce_min_sync(0xffffffffu, cand);   // < NPTS <= 4096

        const int buf = (it & 1) * NW;
        const unsigned int tag = (unsigned int)it & 0xffffu;
        unsigned long long part = ((unsigned long long)wmax << 32)
                                | ((unsigned long long)tag << 16)
                                | (unsigned long long)(0xffffu - wmin);
        if (lane == 0) vred[buf + wid] = part;

        // spin until all NW slots carry this iteration's tag
        unsigned long long v = 0;
        bool ok = (lane >= NW);
        do {
            if (!ok) {
                v = vred[buf + lane];
                ok = (((unsigned int)(v >> 16)) & 0xffffu) == tag;
            }
        } while (!__all_sync(0xffffffffu, ok));

        // lexicographic (hi=dist, lo16=~idx) max via 2x REDUX (tags equal)
        unsigned int hv = (lane < NW) ? (unsigned int)(v >> 32) : 0u;
        unsigned int mh = __reduce_max_sync(0xffffffffu, hv);
        unsigned int lv = (lane < NW && hv == mh) ? ((unsigned int)v & 0xffffu) : 0u;
        unsigned int ml = __reduce_max_sync(0xffffffffu, lv);
        far = (int)(0xffffu - ml);
    }
    __syncthreads();

    // fused gather epilogue: indices + pts(+norm) + (B,3,M) xyz
    for (int j = t; j < M; j += TPB) {
        int src = sidx[j];
        float4 p = spts[src];
        out[(size_t)b * M + j] = src;
        ptsOut[(size_t)b * M + j] = p;
        out_xyz[((size_t)b * 3 + 0) * M + j] = p.x;
        out_xyz[((size_t)b * 3 + 1) * M + j] = p.y;
        out_xyz[((size_t)b * 3 + 2) * M + j] = p.z;
    }
}

constexpr size_t fps_smem_bytes(int npts, int m)
{
    return (size_t)npts * 16 + (size_t)m * 4 + 512;
}

// ---------------------------------------------------------------------------
// feature gather (main stream, after FPS indices are ready)
// ---------------------------------------------------------------------------
__global__ void k_gather_feat(const int* __restrict__ fidx, const float* __restrict__ fIn,
                              int Nin, int Nout, int Cf, float* __restrict__ fOut)
{
    int i = blockIdx.x * 256 + threadIdx.x;
    int total = BATCH * Nout * Cf;
    if (i >= total) return;
    int c = i % Cf;
    int j = (i / Cf) % Nout;
    int b = i / (Cf * Nout);
    int src = fidx[(size_t)b * Nout + j];
    fOut[i] = fIn[((size_t)b * Nin + src) * Cf + c];
}

// ---------------------------------------------------------------------------
// edge-conv:  h[o,n,k] = W_l . (f_nbr - f_q)  +  W_r . f_q
// Block: 4 points x 16 neighbors = 64 columns, 256 threads.
// Emits per-block GroupNorm partial sums (deterministic order).
// ---------------------------------------------------------------------------
template <int C, int O>
__global__ void k_conv(const float* __restrict__ fk, const float* __restrict__ fq,
                       const int* __restrict__ knn, const float* __restrict__ w,
                       int Nq, int Nk, float* __restrict__ h,
                       float* __restrict__ psum, float* __restrict__ psq)
{
    constexpr int TM = O / 16;
    constexpr int C4 = C / 4;
    extern __shared__ float smem[];
    float4* sW4  = (float4*)smem;             // O*C4      (left half of w)
    float4* sD4  = sW4 + O * C4;              // C4*64     [c4][col]
    float4* sFq4 = sD4 + C4 * 64;             // 4*C4
    float*  sBase = (float*)(sFq4 + 4 * C4);  // 4*O
    float*  sRed  = sBase + 4 * O;            // 16
    int*    sIdx  = (int*)(sRed + 16);        // 64

    const int b = blockIdx.y;
    const int n0 = blockIdx.x * 4;
    const int tid = threadIdx.x;

    for (int j = tid; j < O * C4; j += 256) {
        int o = j / C4, c4 = j % C4;
        sW4[j] = *(const float4*)(w + (size_t)o * (2 * C) + c4 * 4);
    }
    for (int j = tid; j < 4 * C4; j += 256) {
        int pt = j / C4, c4 = j % C4;
        sFq4[j] = *(const float4*)(fq + ((size_t)b * Nq + n0 + pt) * C + c4 * 4);
    }
    if (tid < 64)
        sIdx[tid] = knn[((size_t)b * Nq + n0 + (tid >> 4)) * 16 + (tid & 15)];
    __syncthreads();

    for (int j = tid; j < C4 * 64; j += 256) {
        int col = j & 63, c4 = j >> 6;
        int src = sIdx[col];
        float4 kv = *(const float4*)(fk + ((size_t)b * Nk + src) * C + c4 * 4);
        float4 qv = sFq4[(col >> 4) * C4 + c4];
        sD4[c4 * 64 + col] = make_float4(kv.x - qv.x, kv.y - qv.y, kv.z - qv.z, kv.w - qv.w);
    }
    const float* sFq = (const float*)sFq4;
    for (int j = tid; j < 4 * O; j += 256) {
        int o = j >> 2, pt = j & 3;
        const float* wr = w + (size_t)o * (2 * C) + C;
        float s = 0.f;
#pragma unroll 4
        for (int c = 0; c < C; ++c) s = fmaf(wr[c], sFq[pt * C + c], s);
        sBase[pt * O + o] = s;
    }
    __syncthreads();

    const int og = tid >> 4, cg = tid & 15;
    const int o0 = og * TM, col0 = cg * 4;
    float acc[TM][4];
#pragma unroll
    for (int m = 0; m < TM; ++m)
#pragma unroll
        for (int i = 0; i < 4; ++i) acc[m][i] = 0.f;

#pragma unroll
    for (int c4 = 0; c4 < C4; ++c4) {
        float4 d0 = sD4[c4 * 64 + col0 + 0];
        float4 d1 = sD4[c4 * 64 + col0 + 1];
        float4 d2 = sD4[c4 * 64 + col0 + 2];
        float4 d3 = sD4[c4 * 64 + col0 + 3];
#pragma unroll
        for (int m = 0; m < TM; ++m) {
            float4 wv = sW4[(o0 + m) * C4 + c4];
            acc[m][0] += wv.x * d0.x + wv.y * d0.y + wv.z * d0.z + wv.w * d0.w;
            acc[m][1] += wv.x * d1.x + wv.y * d1.y + wv.z * d1.z + wv.w * d1.w;
            acc[m][2] += wv.x * d2.x + wv.y * d2.y + wv.z * d2.z + wv.w * d2.w;
            acc[m][3] += wv.x * d3.x + wv.y * d3.y + wv.z * d3.z + wv.w * d3.w;
        }
    }

    const int pt = col0 >> 4;
    const int kk0 = col0 & 15;
    const int n = n0 + pt;
    float lsum = 0.f, lsq = 0.f;
#pragma unroll
    for (int m = 0; m < TM; ++m) {
        int o = o0 + m;
        float bs = sBase[pt * O + o];
        float4 hv = make_float4(acc[m][0] + bs, acc[m][1] + bs, acc[m][2] + bs, acc[m][3] + bs);
        lsum += hv.x + hv.y + hv.z + hv.w;
        lsq  += hv.x * hv.x + hv.y * hv.y + hv.z * hv.z + hv.w * hv.w;
        *(float4*)(h + ((((size_t)b * O + o) * Nq + n) * 16 + kk0)) = hv;
    }
#pragma unroll
    for (int off = 16; off; off >>= 1) {
        lsum += __shfl_down_sync(0xffffffffu, lsum, off);
        lsq  += __shfl_down_sync(0xffffffffu, lsq, off);
    }
    const int warp = tid >> 5, lane = tid & 31;
    if (lane == 0) { sRed[warp] = lsum; sRed[8 + warp] = lsq; }
    __syncthreads();
    if (tid < 4) {
        float s = sRed[2 * tid] + sRed[2 * tid + 1];
        float q = sRed[8 + 2 * tid] + sRed[8 + 2 * tid + 1];
        psum[((size_t)b * 4 + tid) * 1024 + blockIdx.x] = s;
        psq [((size_t)b * 4 + tid) * 1024 + blockIdx.x] = q;
    }
}

constexpr size_t conv_smem_bytes(int C, int O)
{
    return (size_t)(O * (C / 4) + (C / 4) * 64 + 4 * (C / 4)) * 16 +
           (size_t)(4 * O + 16) * 4 + 64 * 4;
}

// ---------------------------------------------------------------------------
// GroupNorm stats finalize (fixed-order deterministic reduction), grid = 16
// ---------------------------------------------------------------------------
__global__ void k_stats(const float* __restrict__ psum, const float* __restrict__ psq,
                        int nblk, float inv_cnt, float2* __restrict__ stats)
{
    int bg = blockIdx.x;
    const float* ps = psum + (size_t)bg * 1024;
    const float* pq = psq  + (size_t)bg * 1024;
    float s = 0.f, q = 0.f;
    for (int i = threadIdx.x; i < nblk; i += 256) { s += ps[i]; q += pq[i]; }
    __shared__ float shs[8], shq[8];
#pragma unroll
    for (int off = 16; off; off >>= 1) {
        s += __shfl_down_sync(0xffffffffu, s, off);
        q += __shfl_down_sync(0xffffffffu, q, off);
    }
    int warp = threadIdx.x >> 5, lane = threadIdx.x & 31;
    if (lane == 0) { shs[warp] = s; shq[warp] = q; }
    __syncthreads();
    if (threadIdx.x == 0) {
        float S = 0.f, Q = 0.f;
#pragma unroll
        for (int i = 0; i < 8; ++i) { S += shs[i]; Q += shq[i]; }
        float mean = S * inv_cnt;
        float var = Q * inv_cnt - mean * mean;
        stats[bg] = make_float2(mean, rsqrtf(var + 1e-5f));
    }
}

// ---------------------------------------------------------------------------
// normalize + affine + leaky(0.2) + max over k=16
// ---------------------------------------------------------------------------
template <int O>
__global__ void k_normmax(const float* __restrict__ h, const float2* __restrict__ stats,
                          const float* __restrict__ gw, const float* __restrict__ gb,
                          int Nq, float* __restrict__ out_nc, float* __restrict__ out_cn)
{
    int i = blockIdx.x * 256 + threadIdx.x;
    int total = BATCH * O * Nq;
    if (i >= total) return;
    int n = i % Nq;
    int o = (i / Nq) % O;
    int b = i / (Nq * O);
    float2 st = stats[b * 4 + o / (O / 4)];
    float wv = gw[o], bv = gb[o];
    const float4* hp = (const float4*)(h + (size_t)i * 16);
    float mx = -3.4e38f;
#pragma unroll
    for (int k4 = 0; k4 < 4; ++k4) {
        float4 v4 = hp[k4];
        float vals[4] = { v4.x, v4.y, v4.z, v4.w };
#pragma unroll
        for (int t = 0; t < 4; ++t) {
            float v = (vals[t] - st.x) * st.y * wv + bv;
            v = v > 0.f ? v : 0.2f * v;
            mx = fmaxf(mx, v);
        }
    }
    if (out_nc) out_nc[((size_t)b * Nq + n) * O + o] = mx;
    if (out_cn) out_cn[((size_t)b * O + o) * Nq + n] = mx;
}

// ---------------------------------------------------------------------------
// host orchestration: 3 streams — main (knn1+convs), side (FPS), knnB (knn3)
// knn2/knn4 are row-gathers of knn1/knn3 (bit-identical, see k_knn_gather).
// ---------------------------------------------------------------------------
extern "C" void kernel_launch(void* const* d_in, const int* in_sizes, int n_in,
                              void* d_out, int out_size)
{
    const float* x    = (const float*)d_in[0];
    const float* w_in = (const float*)d_in[1];
    const float* b_in = (const float*)d_in[2];
    const float* w1   = (const float*)d_in[3];
    const float* g1w  = (const float*)d_in[4];
    const float* g1b  = (const float*)d_in[5];
    const float* w2   = (const float*)d_in[6];
    const float* g2w  = (const float*)d_in[7];
    const float* g2b  = (const float*)d_in[8];
    const float* w3   = (const float*)d_in[9];
    const float* g3w  = (const float*)d_in[10];
    const float* g3b  = (const float*)d_in[11];
    const float* w4   = (const float*)d_in[12];
    const float* g4w  = (const float*)d_in[13];
    const float* g4b  = (const float*)d_in[14];

    float* out = (float*)d_out;
    float* out_coor   = out + OUT_COOR;
    float* out_f      = out + OUT_F;
    float* out_xyz1   = out + OUT_XYZ1;
    float* out_point1 = out + OUT_POINT1;
    float* out_inpc   = out + OUT_INPC;

    float  *f0, *h, *fa, *fqa, *fb, *fc, *fqb, *psum, *psq;
    float4 *pts0, *pts1, *pts2;
    int    *knn1, *knn2, *knn3, *knn4, *fps1, *fps2;
    float2 *stats;
    cudaGetSymbolAddress((void**)&f0,    g_f0);
    cudaGetSymbolAddress((void**)&pts0,  g_pts0);
    cudaGetSymbolAddress((void**)&knn1,  g_knn1);
    cudaGetSymbolAddress((void**)&knn2,  g_knn2);
    cudaGetSymbolAddress((void**)&knn3,  g_knn3);
    cudaGetSymbolAddress((void**)&knn4,  g_knn4);
    cudaGetSymbolAddress((void**)&h,     g_h);
    cudaGetSymbolAddress((void**)&fa,    g_fa);
    cudaGetSymbolAddress((void**)&fps1,  g_fps1);
    cudaGetSymbolAddress((void**)&pts1,  g_pts1);
    cudaGetSymbolAddress((void**)&fqa,   g_fqa);
    cudaGetSymbolAddress((void**)&fb,    g_fb);
    cudaGetSymbolAddress((void**)&fc,    g_fc);
    cudaGetSymbolAddress((void**)&fps2,  g_fps2);
    cudaGetSymbolAddress((void**)&pts2,  g_pts2);
    cudaGetSymbolAddress((void**)&fqb,   g_fqb);
    cudaGetSymbolAddress((void**)&psum,  g_psum);
    cudaGetSymbolAddress((void**)&psq,   g_psq);
    cudaGetSymbolAddress((void**)&stats, g_stats);

    cudaFuncSetAttribute((const void*)k_conv<8, 32>,
        cudaFuncAttributeMaxDynamicSharedMemorySize, (int)conv_smem_bytes(8, 32));
    cudaFuncSetAttribute((const void*)k_conv<32, 64>,
        cudaFuncAttributeMaxDynamicSharedMemorySize, (int)conv_smem_bytes(32, 64));
    cudaFuncSetAttribute((const void*)k_conv<64, 64>,
        cudaFuncAttributeMaxDynamicSharedMemorySize, (int)conv_smem_bytes(64, 64));
    cudaFuncSetAttribute((const void*)k_conv<64, 128>,
        cudaFuncAttributeMaxDynamicSharedMemorySize, (int)conv_smem_bytes(64, 128));
    cudaFuncSetAttribute((const void*)k_fps<N0, N1, 512>,
        cudaFuncAttributeMaxDynamicSharedMemorySize, (int)FPS_SMEM_PAD);
    cudaFuncSetAttribute((const void*)k_fps<N1, N2, 256>,
        cudaFuncAttributeMaxDynamicSharedMemorySize, (int)fps_smem_bytes(N1, N2));

    // one-time host resources for the capture-time stream forks
    static cudaStream_t sSide = nullptr, sKnnB = nullptr;
    static cudaEvent_t  eFork = nullptr, eJ1 = nullptr, eJ2 = nullptr, eK3 = nullptr;
    if (sSide == nullptr) {
        cudaStreamCreateWithFlags(&sSide, cudaStreamNonBlocking);
        cudaStreamCreateWithFlags(&sKnnB, cudaStreamNonBlocking);
        cudaEventCreateWithFlags(&eFork, cudaEventDisableTiming);
        cudaEventCreateWithFlags(&eJ1,   cudaEventDisableTiming);
        cudaEventCreateWithFlags(&eJ2,   cudaEventDisableTiming);
        cudaEventCreateWithFlags(&eK3,   cudaEventDisableTiming);
    }

    const float inv_cnt = 1.0f / 524288.0f;   // (O/4)*Nq*16, identical every stage

    // ---- stage 0 (main): input MLP + point norms + inpc_f ----
    k_prep0<<<(BATCH * N0 + 255) / 256, 256>>>(x, w_in, b_in, f0, pts0, out_inpc);
    cudaEventRecord(eFork, 0);

    // ---- side stream: fps1 (512 thr, padded) -> fps2 (256 thr, exact smem) ----
    cudaStreamWaitEvent(sSide, eFork, 0);
    k_fps<N0, N1, 512><<<BATCH, 512, FPS_SMEM_PAD, sSide>>>(pts0, fps1, pts1, out_xyz1);
    cudaEventRecord(eJ1, sSide);
    k_fps<N1, N2, 256><<<BATCH, 256, fps_smem_bytes(N1, N2), sSide>>>(
        pts1, fps2, pts2, out_coor);
    cudaEventRecord(eJ2, sSide);

    // ---- knnB stream: knn3 after pts1 (hidden under fps2) ----
    cudaStreamWaitEvent(sKnnB, eJ1, 0);
    k_knn<<<dim3(N1 / 32, BATCH), 128, 0, sKnnB>>>(pts1, pts1, N1, N1, knn3);
    cudaEventRecord(eK3, sKnnB);

    // ---- main: block 1 (independent of FPS; hidden under fps1) ----
    k_knn<<<dim3(N0 / 32, BATCH), 128>>>(pts0, pts0, N0, N0, knn1);
    k_conv<8, 32><<<dim3(N0 / 4, BATCH), 256, conv_smem_bytes(8, 32)>>>(
        f0, f0, knn1, w1, N0, N0, h, psum, psq);
    k_stats<<<16, 256>>>(psum, psq, N0 / 4, inv_cnt, stats);
    k_normmax<32><<<(BATCH * 32 * N0 + 255) / 256, 256>>>(
        h, stats, g1w, g1b, N0, fa, nullptr);

    // ---- block 2: knn2 = knn1 rows gathered by fps1; fqa gather; conv ----
    cudaStreamWaitEvent(0, eJ1, 0);
    k_knn_gather<<<(BATCH * N1 * 16 + 255) / 256, 256>>>(fps1, knn1, N0, N1, knn2);
    k_gather_feat<<<(BATCH * N1 * 32 + 255) / 256, 256>>>(fps1, fa, N0, N1, 32, fqa);
    k_conv<32, 64><<<dim3(N1 / 4, BATCH), 256, conv_smem_bytes(32, 64)>>>(
        fa, fqa, knn2, w2, N1, N0, h, psum, psq);
    k_stats<<<16, 256>>>(psum, psq, N1 / 4, inv_cnt, stats);
    k_normmax<64><<<(BATCH * 64 * N1 + 255) / 256, 256>>>(
        h, stats, g2w, g2b, N1, fb, out_point1);

    // ---- block 3: needs knn3 ----
    cudaStreamWaitEvent(0, eK3, 0);
    k_conv<64, 64><<<dim3(N1 / 4, BATCH), 256, conv_smem_bytes(64, 64)>>>(
        fb, fb, knn3, w3, N1, N1, h, psum, psq);
    k_stats<<<16, 256>>>(psum, psq, N1 / 4, inv_cnt, stats);
    k_normmax<64><<<(BATCH * 64 * N1 + 255) / 256, 256>>>(
        h, stats, g3w, g3b, N1, fc, nullptr);

    // ---- block 4: knn4 = knn3 rows gathered by fps2; fqb gather; conv ----
    cudaStreamWaitEvent(0, eJ2, 0);
    k_knn_gather<<<(BATCH * N2 * 16 + 255) / 256, 256>>>(fps2, knn3, N1, N2, knn4);
    k_gather_feat<<<(BATCH * N2 * 64 + 255) / 256, 256>>>(fps2, fc, N1, N2, 64, fqb);
    k_conv<64, 128><<<dim3(N2 / 4, BATCH), 256, conv_smem_bytes(64, 128)>>>(
        fc, fqb, knn4, w4, N2, N1, h, psum, psq);
    k_stats<<<16, 256>>>(psum, psq, N2 / 4, inv_cnt, stats);
    k_normmax<128><<<(BATCH * 128 * N2 + 255) / 256, 256>>>(
        h, stats, g4w, g4b, N2, nullptr, out_f);
}

// round 17
// speedup vs baseline: 1.1823x; 1.1823x over previous
#include <cuda_runtime.h>
#include <cstdint>

// ---------------------------------------------------------------------------
// Problem constants
// ---------------------------------------------------------------------------
constexpr int BATCH = 4;
constexpr int N0    = 4096;   // input points
constexpr int N1    = 2048;   // after fps1
constexpr int N2    = 1024;   // after fps2 (DOWN_NUM)

// output layout (floats), tuple flattened in order:
// coor (B,3,1024), f (B,128,1024), xyz1 (B,3,2048), point1 (B,64,2048), inpc_f (B,8,4096)
constexpr size_t OUT_COOR   = 0;
constexpr size_t OUT_F      = OUT_COOR   + (size_t)BATCH * 3 * N2;
constexpr size_t OUT_XYZ1   = OUT_F      + (size_t)BATCH * 128 * N2;
constexpr size_t OUT_POINT1 = OUT_XYZ1   + (size_t)BATCH * 3 * N1;
constexpr size_t OUT_INPC   = OUT_POINT1 + (size_t)BATCH * 64 * N1;

// fps1 smem padding: exclusive SMs (launched onto an idle machine, FIFO).
// fps2 uses EXACT smem so it co-schedules with knn3 and starts immediately.
constexpr size_t FPS_SMEM_PAD = 200 * 1024;

// ---------------------------------------------------------------------------
// Device scratch (static; allocation is forbidden)
// ---------------------------------------------------------------------------
__device__ float  g_f0 [BATCH * N0 * 8];        // (B,N,C)
__device__ float4 g_pts0[BATCH * N0];
__device__ int    g_knn1[BATCH * N0 * 16];
__device__ int    g_knn2[BATCH * N1 * 16];      // gathered from knn1
__device__ int    g_knn3[BATCH * N1 * 16];
__device__ int    g_knn4[BATCH * N2 * 16];      // gathered from knn3
__device__ float  g_h   [BATCH * 32 * N0 * 16]; // reused by all convs (main-stream serial)
__device__ float  g_fa  [BATCH * N0 * 32];      // f1 (B,N,C)
__device__ int    g_fps1[BATCH * N1];
__device__ float4 g_pts1[BATCH * N1];
__device__ float  g_fqa [BATCH * N1 * 32];
__device__ float  g_fb  [BATCH * N1 * 64];      // f2
__device__ float  g_fc  [BATCH * N1 * 64];      // f3
__device__ int    g_fps2[BATCH * N2];
__device__ float4 g_pts2[BATCH * N2];
__device__ float  g_fqb [BATCH * N2 * 64];
__device__ float  g_psum[16 * 1024];
__device__ float  g_psq [16 * 1024];
__device__ float2 g_stats[16];

// monotone float->uint transform (ascending uint order == ascending float order)
__device__ __forceinline__ unsigned int ftrans(float f)
{
    unsigned int b = __float_as_uint(f);
    return (b & 0x80000000u) ? ~b : (b | 0x80000000u);
}

// packed f32x2 helpers (Blackwell): per-lane IEEE rn, bitwise == scalar ops
__device__ __forceinline__ unsigned long long pack2(float lo, float hi)
{
    unsigned long long r;
    asm("mov.b64 %0, {%1, %2};" : "=l"(r)
        : "r"(__float_as_uint(lo)), "r"(__float_as_uint(hi)));
    return r;
}
__device__ __forceinline__ void unpack2(float& lo, float& hi, unsigned long long v)
{
    unsigned int a, b;
    asm("mov.b64 {%0, %1}, %2;" : "=r"(a), "=r"(b) : "l"(v));
    lo = __uint_as_float(a); hi = __uint_as_float(b);
}
__device__ __forceinline__ unsigned long long addx2(unsigned long long a, unsigned long long b)
{
    unsigned long long r;
    asm("add.rn.f32x2 %0, %1, %2;" : "=l"(r) : "l"(a), "l"(b));
    return r;
}
__device__ __forceinline__ unsigned long long mulx2(unsigned long long a, unsigned long long b)
{
    unsigned long long r;
    asm("mul.rn.f32x2 %0, %1, %2;" : "=l"(r) : "l"(a), "l"(b));
    return r;
}

// ---------------------------------------------------------------------------
// prep: f0 = w_in @ x + b_in ; pts0 = (x,y,z,|p|^2) ; write inpc_f output
// ---------------------------------------------------------------------------
__global__ void k_prep0(const float* __restrict__ x, const float* __restrict__ w_in,
                        const float* __restrict__ b_in, float* __restrict__ f0,
                        float4* __restrict__ pts, float* __restrict__ out_inpc)
{
    int i = blockIdx.x * 256 + threadIdx.x;
    if (i >= BATCH * N0) return;
    int b = i / N0, n = i % N0;
    const float* xb = x + (size_t)b * 3 * N0 + n;
    float px = xb[0], py = xb[N0], pz = xb[2 * N0];
    float nrm = __fadd_rn(__fadd_rn(__fmul_rn(px, px), __fmul_rn(py, py)), __fmul_rn(pz, pz));
    pts[i] = make_float4(px, py, pz, nrm);
#pragma unroll
    for (int o = 0; o < 8; ++o) {
        float v = fmaf(w_in[o * 3 + 2], pz, fmaf(w_in[o * 3 + 1], py, w_in[o * 3] * px)) + b_in[o];
        f0[(size_t)i * 8 + o] = v;
        out_inpc[((size_t)b * 8 + o) * N0 + n] = v;
    }
}

// ---------------------------------------------------------------------------
// KNN, segmented x4 (measured-best): 4 threads per query, each scans a
// disjoint quarter of the key range with a private register top-16; stable
// 4-way merge in shared. Block = 128 threads = 32 queries x 4 segments.
// ---------------------------------------------------------------------------
__global__ void k_knn(const float4* __restrict__ ptsq, const float4* __restrict__ ptsk,
                      int Nq, int Nk, int* __restrict__ idx)
{
    constexpr int TILE = 256;
    __shared__ float4 sk[4 * TILE];                 // 16 KB staged keys
    __shared__ unsigned long long sl[32 * 65];      // padded candidate lists

    const int b   = blockIdx.y;
    const int tid = threadIdx.x;
    const int ql  = tid >> 2;          // query within block (0..31)
    const int s   = tid & 3;           // segment
    const int q   = blockIdx.x * 32 + ql;
    const int seglen  = Nk >> 2;
    const int segbase = s * seglen;

    float4 Q = ptsq[(size_t)b * Nq + q];

    float dist[16];
    int   ind [16];
#pragma unroll
    for (int i = 0; i < 16; ++i) { dist[i] = 3.4e38f; ind[i] = 0; }

    for (int t0 = 0; t0 < seglen; t0 += TILE) {
        __syncthreads();
        for (int j = tid; j < 4 * TILE; j += 128)
            sk[j] = ptsk[(size_t)b * Nk + (j >> 8) * seglen + t0 + (j & 255)];
        __syncthreads();
        const float4* mysk = sk + s * TILE;
#pragma unroll 4
        for (int j = 0; j < TILE; ++j) {
            float4 P = mysk[j];
            float dot = fmaf(Q.x, P.x, fmaf(Q.y, P.y, Q.z * P.z));
            float d = fmaf(-2.0f, dot, Q.w + P.w);
            if (d < dist[15]) {
                dist[15] = d; ind[15] = segbase + t0 + j;
#pragma unroll
                for (int t = 15; t > 0; --t) {
                    if (dist[t] < dist[t - 1]) {
                        float td = dist[t]; dist[t] = dist[t - 1]; dist[t - 1] = td;
                        int   ti = ind[t];  ind[t]  = ind[t - 1];  ind[t - 1]  = ti;
                    }
                }
            }
        }
    }

    unsigned long long* L = sl + (size_t)ql * 65 + (size_t)s * 16;
#pragma unroll
    for (int i = 0; i < 16; ++i)
        L[i] = ((unsigned long long)ftrans(dist[i]) << 32) | (unsigned int)ind[i];
    __syncthreads();

    if (s == 0) {
        const unsigned long long* M = sl + (size_t)ql * 65;
        int h0 = 0, h1 = 0, h2 = 0, h3 = 0;
        int* op = idx + ((size_t)b * Nq + q) * 16;
#pragma unroll
        for (int r = 0; r < 16; ++r) {
            unsigned long long b0 = (h0 < 16) ? M[h0]      : ~0ULL;
            unsigned long long b1 = (h1 < 16) ? M[16 + h1] : ~0ULL;
            unsigned long long b2 = (h2 < 16) ? M[32 + h2] : ~0ULL;
            unsigned long long b3 = (h3 < 16) ? M[48 + h3] : ~0ULL;
            unsigned long long m01 = b0 < b1 ? b0 : b1;
            unsigned long long m23 = b2 < b3 ? b2 : b3;
            unsigned long long m   = m01 < m23 ? m01 : m23;
            op[r] = (int)(unsigned int)m;
            if      (m == b0) ++h0;
            else if (m == b1) ++h1;
            else if (m == b2) ++h2;
            else              ++h3;
        }
    }
}

// ---------------------------------------------------------------------------
// fused post-FPS gather: knnOut rows (knnIn[fidx]) + feature rows (fIn[fidx]).
// One launch instead of two on the serial tail. Bit-identical to the pair.
// ---------------------------------------------------------------------------
__global__ void k_gather_both(const int* __restrict__ fidx,
                              const int* __restrict__ knnIn, int NinQ,
                              const float* __restrict__ fIn, int Nin, int Cf,
                              int Nout, int* __restrict__ knnOut,
                              float* __restrict__ fOut)
{
    int i = blockIdx.x * 256 + threadIdx.x;
    int totalF = BATCH * Nout * Cf;
    int totalK = BATCH * Nout * 16;
    if (i < totalF) {
        int c = i % Cf;
        int j = (i / Cf) % Nout;
        int b = i / (Cf * Nout);
        int src = fidx[(size_t)b * Nout + j];
        fOut[i] = fIn[((size_t)b * Nin + src) * Cf + c];
    } else if (i - totalF < totalK) {
        int k = i - totalF;
        int r = k & 15;
        int j = (k >> 4) % Nout;
        int b = k / (Nout * 16);
        int src = fidx[(size_t)b * Nout + j];
        knnOut[k] = knnIn[((size_t)b * NinQ + src) * 16 + r];
    }
}

// ---------------------------------------------------------------------------
// FPS + fused gather epilogue. One block per batch, TPB templated.
// Points in shared; packed f32x2 math (bitwise == scalar rn); warp argmax via
// 2x REDUX; block finalize via lane-parallel split hi/lo REDUX scan
// (lexicographic max on (dist-bits, ~idx) -> first-index tie-break exact).
// One __syncthreads per iteration (measured-best synchronization).
// ---------------------------------------------------------------------------
template <int NPTS, int M, int TPB>
__global__ void k_fps(const float4* __restrict__ pts, int* __restrict__ out,
                      float4* __restrict__ ptsOut, float* __restrict__ out_xyz)
{
    constexpr int PPT = NPTS / TPB;
    constexpr int PP  = PPT / 2;
    constexpr int NW  = TPB / 32;
    extern __shared__ float4 spts[];                         // NPTS float4
    int* sidx = (int*)(spts + NPTS);                         // M ints
    unsigned int* sredH = (unsigned int*)(sidx + M);         // [2][NW]
    unsigned int* sredL = sredH + 2 * NW;                    // [2][NW]

    const int b = blockIdx.x, t = threadIdx.x;
    const int wid = t >> 5, lane = t & 31;

    unsigned long long lx2[PP], ly2[PP], lz2[PP];
    float ld[PPT];
#pragma unroll
    for (int i = 0; i < PP; ++i) {
        float4 p0 = pts[(size_t)b * NPTS + (2 * i) * TPB + t];
        float4 p1 = pts[(size_t)b * NPTS + (2 * i + 1) * TPB + t];
        lx2[i] = pack2(p0.x, p1.x);
        ly2[i] = pack2(p0.y, p1.y);
        lz2[i] = pack2(p0.z, p1.z);
        ld[2 * i] = 1e10f; ld[2 * i + 1] = 1e10f;
        spts[(2 * i) * TPB + t] = p0;
        spts[(2 * i + 1) * TPB + t] = p1;
    }
    __syncthreads();

    int far = 0;
    for (int it = 0; it < M; ++it) {
        if (t == 0) sidx[it] = far;
        float4 c = spts[far];
        unsigned long long ncx2 = pack2(-c.x, -c.x);
        unsigned long long ncy2 = pack2(-c.y, -c.y);
        unsigned long long ncz2 = pack2(-c.z, -c.z);

        float bv = -1.0f; int bi = 0;
#pragma unroll
        for (int i = 0; i < PP; ++i) {
            unsigned long long dx2 = addx2(lx2[i], ncx2);   // == __fsub_rn
            unsigned long long dy2 = addx2(ly2[i], ncy2);
            unsigned long long dz2 = addx2(lz2[i], ncz2);
            unsigned long long xx2 = mulx2(dx2, dx2);
            unsigned long long yy2 = mulx2(dy2, dy2);
            unsigned long long zz2 = mulx2(dz2, dz2);
            unsigned long long s2  = addx2(xx2, yy2);
            unsigned long long d2  = addx2(s2, zz2);
            float d0, d1; unpack2(d0, d1, d2);
            float nd0 = fminf(ld[2 * i], d0);     ld[2 * i] = nd0;
            float nd1 = fminf(ld[2 * i + 1], d1); ld[2 * i + 1] = nd1;
            if (nd0 > bv) { bv = nd0; bi = (2 * i) * TPB + t; }
            if (nd1 > bv) { bv = nd1; bi = (2 * i + 1) * TPB + t; }
        }
        // warp argmax: dist >= 0 so float bits compare as uints
        unsigned int vb   = __float_as_uint(bv);
        unsigned int wmax = __reduce_max_sync(0xffffffffu, vb);
        unsigned int cand = (vb == wmax) ? (unsigned int)bi : 0xffffffffu;
        unsigned int wmin = __reduce_min_sync(0xffffffffu, cand);
        const int buf = (it & 1) * NW;
        if (lane == 0) {
            sredH[buf + wid] = wmax;
            sredL[buf + wid] = 0xffffffffu - wmin;
        }
        __syncthreads();

        // lane-parallel block argmax: lexicographic (hi, lo) max via 2x REDUX
        unsigned int hv = (lane < NW) ? sredH[buf + lane] : 0u;
        unsigned int mh = __reduce_max_sync(0xffffffffu, hv);
        unsigned int lv = (lane < NW && hv == mh) ? sredL[buf + lane] : 0u;
        unsigned int ml = __reduce_max_sync(0xffffffffu, lv);
        far = (int)(0xffffffffu - ml);
    }
    __syncthreads();

    // fused gather epilogue: indices + pts(+norm) + (B,3,M) xyz
    for (int j = t; j < M; j += TPB) {
        int src = sidx[j];
        float4 p = spts[src];
        out[(size_t)b * M + j] = src;
        ptsOut[(size_t)b * M + j] = p;
        out_xyz[((size_t)b * 3 + 0) * M + j] = p.x;
        out_xyz[((size_t)b * 3 + 1) * M + j] = p.y;
        out_xyz[((size_t)b * 3 + 2) * M + j] = p.z;
    }
}

constexpr size_t fps_smem_bytes(int npts, int m)
{
    return (size_t)npts * 16 + (size_t)m * 4 + 512;
}

// ---------------------------------------------------------------------------
// edge-conv:  h[o,n,k] = W_l . (f_nbr - f_q)  +  W_r . f_q
// Block: 4 points x 16 neighbors = 64 columns, 256 threads.
// Emits per-block GroupNorm partial sums (deterministic order).
// ---------------------------------------------------------------------------
template <int C, int O>
__global__ void k_conv(const float* __restrict__ fk, const float* __restrict__ fq,
                       const int* __restrict__ knn, const float* __restrict__ w,
                       int Nq, int Nk, float* __restrict__ h,
                       float* __restrict__ psum, float* __restrict__ psq)
{
    constexpr int TM = O / 16;
    constexpr int C4 = C / 4;
    extern __shared__ float smem[];
    float4* sW4  = (float4*)smem;             // O*C4      (left half of w)
    float4* sD4  = sW4 + O * C4;              // C4*64     [c4][col]
    float4* sFq4 = sD4 + C4 * 64;             // 4*C4
    float*  sBase = (float*)(sFq4 + 4 * C4);  // 4*O
    float*  sRed  = sBase + 4 * O;            // 16
    int*    sIdx  = (int*)(sRed + 16);        // 64

    const int b = blockIdx.y;
    const int n0 = blockIdx.x * 4;
    const int tid = threadIdx.x;

    for (int j = tid; j < O * C4; j += 256) {
        int o = j / C4, c4 = j % C4;
        sW4[j] = *(const float4*)(w + (size_t)o * (2 * C) + c4 * 4);
    }
    for (int j = tid; j < 4 * C4; j += 256) {
        int pt = j / C4, c4 = j % C4;
        sFq4[j] = *(const float4*)(fq + ((size_t)b * Nq + n0 + pt) * C + c4 * 4);
    }
    if (tid < 64)
        sIdx[tid] = knn[((size_t)b * Nq + n0 + (tid >> 4)) * 16 + (tid & 15)];
    __syncthreads();

    for (int j = tid; j < C4 * 64; j += 256) {
        int col = j & 63, c4 = j >> 6;
        int src = sIdx[col];
        float4 kv = *(const float4*)(fk + ((size_t)b * Nk + src) * C + c4 * 4);
        float4 qv = sFq4[(col >> 4) * C4 + c4];
        sD4[c4 * 64 + col] = make_float4(kv.x - qv.x, kv.y - qv.y, kv.z - qv.z, kv.w - qv.w);
    }
    const float* sFq = (const float*)sFq4;
    for (int j = tid; j < 4 * O; j += 256) {
        int o = j >> 2, pt = j & 3;
        const float* wr = w + (size_t)o * (2 * C) + C;
        float s = 0.f;
#pragma unroll 4
        for (int c = 0; c < C; ++c) s = fmaf(wr[c], sFq[pt * C + c], s);
        sBase[pt * O + o] = s;
    }
    __syncthreads();

    const int og = tid >> 4, cg = tid & 15;
    const int o0 = og * TM, col0 = cg * 4;
    float acc[TM][4];
#pragma unroll
    for (int m = 0; m < TM; ++m)
#pragma unroll
        for (int i = 0; i < 4; ++i) acc[m][i] = 0.f;

#pragma unroll
    for (int c4 = 0; c4 < C4; ++c4) {
        float4 d0 = sD4[c4 * 64 + col0 + 0];
        float4 d1 = sD4[c4 * 64 + col0 + 1];
        float4 d2 = sD4[c4 * 64 + col0 + 2];
        float4 d3 = sD4[c4 * 64 + col0 + 3];
#pragma unroll
        for (int m = 0; m < TM; ++m) {
            float4 wv = sW4[(o0 + m) * C4 + c4];
            acc[m][0] += wv.x * d0.x + wv.y * d0.y + wv.z * d0.z + wv.w * d0.w;
            acc[m][1] += wv.x * d1.x + wv.y * d1.y + wv.z * d1.z + wv.w * d1.w;
            acc[m][2] += wv.x * d2.x + wv.y * d2.y + wv.z * d2.z + wv.w * d2.w;
            acc[m][3] += wv.x * d3.x + wv.y * d3.y + wv.z * d3.z + wv.w * d3.w;
        }
    }

    const int pt = col0 >> 4;
    const int kk0 = col0 & 15;
    const int n = n0 + pt;
    float lsum = 0.f, lsq = 0.f;
#pragma unroll
    for (int m = 0; m < TM; ++m) {
        int o = o0 + m;
        float bs = sBase[pt * O + o];
        float4 hv = make_float4(acc[m][0] + bs, acc[m][1] + bs, acc[m][2] + bs, acc[m][3] + bs);
        lsum += hv.x + hv.y + hv.z + hv.w;
        lsq  += hv.x * hv.x + hv.y * hv.y + hv.z * hv.z + hv.w * hv.w;
        *(float4*)(h + ((((size_t)b * O + o) * Nq + n) * 16 + kk0)) = hv;
    }
#pragma unroll
    for (int off = 16; off; off >>= 1) {
        lsum += __shfl_down_sync(0xffffffffu, lsum, off);
        lsq  += __shfl_down_sync(0xffffffffu, lsq, off);
    }
    const int warp = tid >> 5, lane = tid & 31;
    if (lane == 0) { sRed[warp] = lsum; sRed[8 + warp] = lsq; }
    __syncthreads();
    if (tid < 4) {
        float s = sRed[2 * tid] + sRed[2 * tid + 1];
        float q = sRed[8 + 2 * tid] + sRed[8 + 2 * tid + 1];
        psum[((size_t)b * 4 + tid) * 1024 + blockIdx.x] = s;
        psq [((size_t)b * 4 + tid) * 1024 + blockIdx.x] = q;
    }
}

constexpr size_t conv_smem_bytes(int C, int O)
{
    return (size_t)(O * (C / 4) + (C / 4) * 64 + 4 * (C / 4)) * 16 +
           (size_t)(4 * O + 16) * 4 + 64 * 4;
}

// ---------------------------------------------------------------------------
// GroupNorm stats finalize (fixed-order deterministic reduction), grid = 16
// ---------------------------------------------------------------------------
__global__ void k_stats(const float* __restrict__ psum, const float* __restrict__ psq,
                        int nblk, float inv_cnt, float2* __restrict__ stats)
{
    int bg = blockIdx.x;
    const float* ps = psum + (size_t)bg * 1024;
    const float* pq = psq  + (size_t)bg * 1024;
    float s = 0.f, q = 0.f;
    for (int i = threadIdx.x; i < nblk; i += 256) { s += ps[i]; q += pq[i]; }
    __shared__ float shs[8], shq[8];
#pragma unroll
    for (int off = 16; off; off >>= 1) {
        s += __shfl_down_sync(0xffffffffu, s, off);
        q += __shfl_down_sync(0xffffffffu, q, off);
    }
    int warp = threadIdx.x >> 5, lane = threadIdx.x & 31;
    if (lane == 0) { shs[warp] = s; shq[warp] = q; }
    __syncthreads();
    if (threadIdx.x == 0) {
        float S = 0.f, Q = 0.f;
#pragma unroll
        for (int i = 0; i < 8; ++i) { S += shs[i]; Q += shq[i]; }
        float mean = S * inv_cnt;
        float var = Q * inv_cnt - mean * mean;
        stats[bg] = make_float2(mean, rsqrtf(var + 1e-5f));
    }
}

// ---------------------------------------------------------------------------
// normalize + affine + leaky(0.2) + max over k=16
// ---------------------------------------------------------------------------
template <int O>
__global__ void k_normmax(const float* __restrict__ h, const float2* __restrict__ stats,
                          const float* __restrict__ gw, const float* __restrict__ gb,
                          int Nq, float* __restrict__ out_nc, float* __restrict__ out_cn)
{
    int i = blockIdx.x * 256 + threadIdx.x;
    int total = BATCH * O * Nq;
    if (i >= total) return;
    int n = i % Nq;
    int o = (i / Nq) % O;
    int b = i / (Nq * O);
    float2 st = stats[b * 4 + o / (O / 4)];
    float wv = gw[o], bv = gb[o];
    const float4* hp = (const float4*)(h + (size_t)i * 16);
    float mx = -3.4e38f;
#pragma unroll
    for (int k4 = 0; k4 < 4; ++k4) {
        float4 v4 = hp[k4];
        float vals[4] = { v4.x, v4.y, v4.z, v4.w };
#pragma unroll
        for (int t = 0; t < 4; ++t) {
            float v = (vals[t] - st.x) * st.y * wv + bv;
            v = v > 0.f ? v : 0.2f * v;
            mx = fmaxf(mx, v);
        }
    }
    if (out_nc) out_nc[((size_t)b * Nq + n) * O + o] = mx;
    if (out_cn) out_cn[((size_t)b * O + o) * Nq + n] = mx;
}

// ---------------------------------------------------------------------------
// host orchestration: 3 streams — main (knn1+convs), side (FPS), knnB (knn3)
// knn2/knn4 are row-gathers of knn1/knn3 (bit-identical), fused with the
// feature gathers into one launch each.
// ---------------------------------------------------------------------------
extern "C" void kernel_launch(void* const* d_in, const int* in_sizes, int n_in,
                              void* d_out, int out_size)
{
    const float* x    = (const float*)d_in[0];
    const float* w_in = (const float*)d_in[1];
    const float* b_in = (const float*)d_in[2];
    const float* w1   = (const float*)d_in[3];
    const float* g1w  = (const float*)d_in[4];
    const float* g1b  = (const float*)d_in[5];
    const float* w2   = (const float*)d_in[6];
    const float* g2w  = (const float*)d_in[7];
    const float* g2b  = (const float*)d_in[8];
    const float* w3   = (const float*)d_in[9];
    const float* g3w  = (const float*)d_in[10];
    const float* g3b  = (const float*)d_in[11];
    const float* w4   = (const float*)d_in[12];
    const float* g4w  = (const float*)d_in[13];
    const float* g4b  = (const float*)d_in[14];

    float* out = (float*)d_out;
    float* out_coor   = out + OUT_COOR;
    float* out_f      = out + OUT_F;
    float* out_xyz1   = out + OUT_XYZ1;
    float* out_point1 = out + OUT_POINT1;
    float* out_inpc   = out + OUT_INPC;

    float  *f0, *h, *fa, *fqa, *fb, *fc, *fqb, *psum, *psq;
    float4 *pts0, *pts1, *pts2;
    int    *knn1, *knn2, *knn3, *knn4, *fps1, *fps2;
    float2 *stats;
    cudaGetSymbolAddress((void**)&f0,    g_f0);
    cudaGetSymbolAddress((void**)&pts0,  g_pts0);
    cudaGetSymbolAddress((void**)&knn1,  g_knn1);
    cudaGetSymbolAddress((void**)&knn2,  g_knn2);
    cudaGetSymbolAddress((void**)&knn3,  g_knn3);
    cudaGetSymbolAddress((void**)&knn4,  g_knn4);
    cudaGetSymbolAddress((void**)&h,     g_h);
    cudaGetSymbolAddress((void**)&fa,    g_fa);
    cudaGetSymbolAddress((void**)&fps1,  g_fps1);
    cudaGetSymbolAddress((void**)&pts1,  g_pts1);
    cudaGetSymbolAddress((void**)&fqa,   g_fqa);
    cudaGetSymbolAddress((void**)&fb,    g_fb);
    cudaGetSymbolAddress((void**)&fc,    g_fc);
    cudaGetSymbolAddress((void**)&fps2,  g_fps2);
    cudaGetSymbolAddress((void**)&pts2,  g_pts2);
    cudaGetSymbolAddress((void**)&fqb,   g_fqb);
    cudaGetSymbolAddress((void**)&psum,  g_psum);
    cudaGetSymbolAddress((void**)&psq,   g_psq);
    cudaGetSymbolAddress((void**)&stats, g_stats);

    cudaFuncSetAttribute((const void*)k_conv<8, 32>,
        cudaFuncAttributeMaxDynamicSharedMemorySize, (int)conv_smem_bytes(8, 32));
    cudaFuncSetAttribute((const void*)k_conv<32, 64>,
        cudaFuncAttributeMaxDynamicSharedMemorySize, (int)conv_smem_bytes(32, 64));
    cudaFuncSetAttribute((const void*)k_conv<64, 64>,
        cudaFuncAttributeMaxDynamicSharedMemorySize, (int)conv_smem_bytes(64, 64));
    cudaFuncSetAttribute((const void*)k_conv<64, 128>,
        cudaFuncAttributeMaxDynamicSharedMemorySize, (int)conv_smem_bytes(64, 128));
    cudaFuncSetAttribute((const void*)k_fps<N0, N1, 512>,
        cudaFuncAttributeMaxDynamicSharedMemorySize, (int)FPS_SMEM_PAD);
    cudaFuncSetAttribute((const void*)k_fps<N1, N2, 256>,
        cudaFuncAttributeMaxDynamicSharedMemorySize, (int)fps_smem_bytes(N1, N2));

    // one-time host resources for the capture-time stream forks
    static cudaStream_t sSide = nullptr, sKnnB = nullptr;
    static cudaEvent_t  eFork = nullptr, eJ1 = nullptr, eJ2 = nullptr, eK3 = nullptr;
    if (sSide == nullptr) {
        cudaStreamCreateWithFlags(&sSide, cudaStreamNonBlocking);
        cudaStreamCreateWithFlags(&sKnnB, cudaStreamNonBlocking);
        cudaEventCreateWithFlags(&eFork, cudaEventDisableTiming);
        cudaEventCreateWithFlags(&eJ1,   cudaEventDisableTiming);
        cudaEventCreateWithFlags(&eJ2,   cudaEventDisableTiming);
        cudaEventCreateWithFlags(&eK3,   cudaEventDisableTiming);
    }

    const float inv_cnt = 1.0f / 524288.0f;   // (O/4)*Nq*16, identical every stage

    // ---- stage 0 (main): input MLP + point norms + inpc_f ----
    k_prep0<<<(BATCH * N0 + 255) / 256, 256>>>(x, w_in, b_in, f0, pts0, out_inpc);
    cudaEventRecord(eFork, 0);

    // ---- side stream: fps1 (512 thr, padded) -> fps2 (256 thr, exact smem) ----
    cudaStreamWaitEvent(sSide, eFork, 0);
    k_fps<N0, N1, 512><<<BATCH, 512, FPS_SMEM_PAD, sSide>>>(pts0, fps1, pts1, out_xyz1);
    cudaEventRecord(eJ1, sSide);
    k_fps<N1, N2, 256><<<BATCH, 256, fps_smem_bytes(N1, N2), sSide>>>(
        pts1, fps2, pts2, out_coor);
    cudaEventRecord(eJ2, sSide);

    // ---- knnB stream: knn3 after pts1 (hidden under fps2) ----
    cudaStreamWaitEvent(sKnnB, eJ1, 0);
    k_knn<<<dim3(N1 / 32, BATCH), 128, 0, sKnnB>>>(pts1, pts1, N1, N1, knn3);
    cudaEventRecord(eK3, sKnnB);

    // ---- main: block 1 (independent of FPS; hidden under fps1) ----
    k_knn<<<dim3(N0 / 32, BATCH), 128>>>(pts0, pts0, N0, N0, knn1);
    k_conv<8, 32><<<dim3(N0 / 4, BATCH), 256, conv_smem_bytes(8, 32)>>>(
        f0, f0, knn1, w1, N0, N0, h, psum, psq);
    k_stats<<<16, 256>>>(psum, psq, N0 / 4, inv_cnt, stats);
    k_normmax<32><<<(BATCH * 32 * N0 + 255) / 256, 256>>>(
        h, stats, g1w, g1b, N0, fa, nullptr);

    // ---- block 2: fused gather (knn2 rows + fqa feats), then conv ----
    cudaStreamWaitEvent(0, eJ1, 0);
    {
        int totalF = BATCH * N1 * 32, totalK = BATCH * N1 * 16;
        k_gather_both<<<(totalF + totalK + 255) / 256, 256>>>(
            fps1, knn1, N0, fa, N0, 32, N1, knn2, fqa);
    }
    k_conv<32, 64><<<dim3(N1 / 4, BATCH), 256, conv_smem_bytes(32, 64)>>>(
        fa, fqa, knn2, w2, N1, N0, h, psum, psq);
    k_stats<<<16, 256>>>(psum, psq, N1 / 4, inv_cnt, stats);
    k_normmax<64><<<(BATCH * 64 * N1 + 255) / 256, 256>>>(
        h, stats, g2w, g2b, N1, fb, out_point1);

    // ---- block 3: needs knn3 ----
    cudaStreamWaitEvent(0, eK3, 0);
    k_conv<64, 64><<<dim3(N1 / 4, BATCH), 256, conv_smem_bytes(64, 64)>>>(
        fb, fb, knn3, w3, N1, N1, h, psum, psq);
    k_stats<<<16, 256>>>(psum, psq, N1 / 4, inv_cnt, stats);
    k_normmax<64><<<(BATCH * 64 * N1 + 255) / 256, 256>>>(
        h, stats, g3w, g3b, N1, fc, nullptr);

    // ---- block 4: fused gather (knn4 rows + fqb feats), then conv ----
    cudaStreamWaitEvent(0, eJ2, 0);
    {
        int totalF = BATCH * N2 * 64, totalK = BATCH * N2 * 16;
        k_gather_both<<<(totalF + totalK + 255) / 256, 256>>>(
            fps2, knn3, N1, fc, N1, 64, N2, knn4, fqb);
    }
    k_conv<64, 128><<<dim3(N2 / 4, BATCH), 256, conv_smem_bytes(64, 128)>>>(
        fc, fqb, knn4, w4, N2, N1, h, psum, psq);
    k_stats<<<16, 256>>>(psum, psq, N2 / 4, inv_cnt, stats);
    k_normmax<128><<<(BATCH * 128 * N2 + 255) / 256, 256>>>(
        h, stats, g4w, g4b, N2, nullptr, out_f);
}